// round 14
// baseline (speedup 1.0000x reference)
#include <cuda_runtime.h>

#define DD 8
#define HH 64
#define TPB 512
#define RPC 256   // rows per CTA (16 warps x 16 rows)

// ---- dynamic shared memory layout (float offsets; all 16B aligned) ----
#define OW1T 0        // [9][64]   W1^T ([d][j]; d==8 is t row)
#define OB1  576      // [64]
#define OW2T 640      // [64][64]  W2^T ([k][j]) forward
#define OW2  4736     // [64][64]  W2   ([j][k]) backward
#define OB2  8832     // [64]
#define OW3T 8896     // [64][8]   W3^T ([k][d])
#define OB3  9408     // [8] (+8 pad)
#define OW1S 9424     // [64] sum_{d<8} W1[k][d]
#define OW3S 9488     // [64] sum_d W3[d][j]
#define OX   9552     // [8][RPC]  x state ([d][row])
#define OH   11600    // [64][RPC] h1 state ([col][row])
#define OG   27984    // [64][RPC] h2 / g_a2 state ([col][row])
#define SMEM_FLOATS 44368
#define SMEM_BYTES  (SMEM_FLOATS * 4)   // 177472 B

typedef unsigned long long u64;
typedef ulonglong2 u64x2;

__device__ __forceinline__ u64 pk2(float a, float b) {
    u64 r; asm("mov.b64 %0, {%1,%2};" : "=l"(r) : "f"(a), "f"(b)); return r;
}
__device__ __forceinline__ void up2(u64 v, float& a, float& b) {
    asm("mov.b64 {%0,%1}, %2;" : "=f"(a), "=f"(b) : "l"(v));
}
__device__ __forceinline__ u64 f2fma(u64 a, u64 b, u64 c) {
    u64 d; asm("fma.rn.f32x2 %0, %1, %2, %3;" : "=l"(d) : "l"(a), "l"(b), "l"(c)); return d;
}
// tanh(x) = 1 - 2/(exp2(2*log2e*x)+1); saturates correctly, ~1e-6 rel err.
__device__ __forceinline__ float fast_tanh(float x) {
    float e; asm("ex2.approx.f32 %0, %1;" : "=f"(e) : "f"(x * 2.88539008177792681472f));
    float r; asm("rcp.approx.f32 %0, %1;" : "=f"(r) : "f"(e + 1.0f));
    return fmaf(-2.0f, r, 1.0f);
}

// 4 packed FMAs for one row's broadcast P against 8 weights (2 u64x2)
#define ROW4(R, P, W0, W1) \
    acc[R][0]=f2fma(P,(W0).x,acc[R][0]); acc[R][1]=f2fma(P,(W0).y,acc[R][1]); \
    acc[R][2]=f2fma(P,(W1).x,acc[R][2]); acc[R][3]=f2fma(P,(W1).y,acc[R][3]);

// k-loop body: state[k][rowb..rowb+3] (LDS.128), 8 weights (2x LDS.128), 16 f2fma
#define MVK(SRCOFF, WOFF, KN) \
    _Pragma("unroll 4") \
    for (int k = 0; k < (KN); k++) { \
        const float4 av = *(const float4*)&dsm[(SRCOFF) + k * RPC + rowb]; \
        const u64 p0 = pk2(av.x, av.x), p1 = pk2(av.y, av.y); \
        const u64 p2 = pk2(av.z, av.z), p3 = pk2(av.w, av.w); \
        const u64* wp = (const u64*)&dsm[(WOFF) + k * HH + colb]; \
        const u64x2 w0 = *(const u64x2*)(wp); \
        const u64x2 w1 = *(const u64x2*)(wp + 2); \
        ROW4(0, p0, w0, w1) \
        ROW4(1, p1, w0, w1) \
        ROW4(2, p2, w0, w1) \
        ROW4(3, p3, w0, w1) \
    }

// init 4x4 accumulators from an 8-wide bias slice (replicated across rows)
#define MV_BIASINIT(BOFF) \
    { const u64* bp = (const u64*)&dsm[(BOFF) + colb]; \
      const u64x2 b0 = *(const u64x2*)(bp), b1 = *(const u64x2*)(bp + 2); \
      _Pragma("unroll") \
      for (int rr = 0; rr < 4; rr++) { \
          acc[rr][0] = b0.x; acc[rr][1] = b0.y; acc[rr][2] = b1.x; acc[rr][3] = b1.y; } }

// tanh + transposed writeback: per colpair, 8 values -> 2 STS.128 columns
#define WB_TANH(OFF) \
    _Pragma("unroll") \
    for (int cp = 0; cp < 4; cp++) { \
        float e0,o0,e1,o1,e2,o2,e3,o3; \
        up2(acc[0][cp], e0, o0); up2(acc[1][cp], e1, o1); \
        up2(acc[2][cp], e2, o2); up2(acc[3][cp], e3, o3); \
        e0 = fast_tanh(e0); o0 = fast_tanh(o0); e1 = fast_tanh(e1); o1 = fast_tanh(o1); \
        e2 = fast_tanh(e2); o2 = fast_tanh(o2); e3 = fast_tanh(e3); o3 = fast_tanh(o3); \
        *(float4*)&dsm[(OFF) + (colb + 2*cp) * RPC + rowb]     = make_float4(e0,e1,e2,e3); \
        *(float4*)&dsm[(OFF) + (colb + 2*cp + 1) * RPC + rowb] = make_float4(o0,o1,o2,o3); \
    }

__global__ void __launch_bounds__(TPB, 1)
cnf_kernel(const float* __restrict__ x0,
           const float* __restrict__ W1g,   // [64][9]
           const float* __restrict__ b1g,   // [64]
           const float* __restrict__ W2g,   // [64][64]
           const float* __restrict__ b2g,   // [64]
           const float* __restrict__ W3g,   // [8][64]
           const float* __restrict__ b3g,   // [8]
           const int*   __restrict__ nsp,
           float* __restrict__ out, int n)
{
    extern __shared__ float dsm[];
    const int tid = threadIdx.x;

    // ---------------- cooperative weight init ----------------
    for (int idx = tid; idx < HH * HH; idx += TPB) {
        int j = idx >> 6, k = idx & 63;
        float v = W2g[idx];
        dsm[OW2 + j * HH + k]  = v;   // [j][k]
        dsm[OW2T + k * HH + j] = v;   // [k][j]
    }
    for (int idx = tid; idx < HH * (DD + 1); idx += TPB) {
        int j = idx / (DD + 1), d = idx % (DD + 1);
        dsm[OW1T + d * HH + j] = W1g[idx];
    }
    for (int idx = tid; idx < HH * DD; idx += TPB) {
        int d = idx >> 6, k = idx & 63;
        dsm[OW3T + k * DD + d] = W3g[idx];
    }
    for (int idx = tid; idx < HH; idx += TPB) {
        dsm[OB1 + idx] = b1g[idx];
        dsm[OB2 + idx] = b2g[idx];
        float s1 = 0.f;
        for (int d = 0; d < DD; d++) s1 += W1g[idx * (DD + 1) + d];
        dsm[OW1S + idx] = s1;
        float s3 = 0.f;
        for (int d = 0; d < DD; d++) s3 += W3g[d * HH + idx];
        dsm[OW3S + idx] = s3;
    }
    if (tid < DD) dsm[OB3 + tid] = b3g[tid];

    // ---------------- x state init ([d][row] transposed) ----------------
    const int base = blockIdx.x * RPC;
    for (int idx = tid; idx < RPC * DD; idx += TPB) {
        int rr = idx >> 3, d = idx & 7;
        int grow = base + rr;
        dsm[OX + d * RPC + rr] = (grow < n) ? x0[grow * DD + d] : 0.f;
    }
    __syncthreads();

    // warp tile coordinates: warp = 16 rows; thread = 4 rows x 8 cols
    const int lane = tid & 31;
    const int warp = tid >> 5;
    const int r4   = lane >> 3;       // 0..3
    const int c8   = lane & 7;        // 0..7
    const int rowb = warp * 16 + r4 * 4;   // first of this thread's 4 rows (CTA-local)
    const int colb = c8 * 8;               // first of this thread's 8 cols

    const int nsteps = nsp ? *nsp : 100;
    const float dt = 1.0f / (float)nsteps;

    float ldr0 = 0.f, ldr1 = 0.f, ldr2 = 0.f, ldr3 = 0.f;

    #pragma unroll 1
    for (int i = 0; i < nsteps; i++) {
        const float t = (float)i * dt;

        #pragma unroll 1
        for (int pass = 0; pass < 2; pass++) {
            // ---- layer 1: OH = tanh(W1 @ [x; t] + b1) ----
            {
                u64 acc[4][4];
                MV_BIASINIT(OB1)
                MVK(OX, OW1T, 8)
                {   // t row (d == 8): same broadcast for all rows
                    const u64 pt = pk2(t, t);
                    const u64* wp = (const u64*)&dsm[OW1T + 8 * HH + colb];
                    const u64x2 w0 = *(const u64x2*)(wp);
                    const u64x2 w1 = *(const u64x2*)(wp + 2);
                    ROW4(0, pt, w0, w1)
                    ROW4(1, pt, w0, w1)
                    ROW4(2, pt, w0, w1)
                    ROW4(3, pt, w0, w1)
                }
                WB_TANH(OH)
            }
            __syncwarp();

            // ---- layer 2 ----
            if (pass == 0) {
                u64 acc[4][4];
                MV_BIASINIT(OB2)
                MVK(OH, OW2T, 64)
                WB_TANH(OG)
            } else {
                // fused: g = tanh(...); OG = w3s * (1 - g^2)  (g_a2 for VJP)
                u64 acc[4][4];
                MV_BIASINIT(OB2)
                MVK(OH, OW2T, 64)
                #pragma unroll
                for (int cp = 0; cp < 4; cp++) {
                    const float wze = dsm[OW3S + colb + 2*cp];
                    const float wzo = dsm[OW3S + colb + 2*cp + 1];
                    float e0,o0,e1,o1,e2,o2,e3,o3;
                    up2(acc[0][cp], e0, o0); up2(acc[1][cp], e1, o1);
                    up2(acc[2][cp], e2, o2); up2(acc[3][cp], e3, o3);
                    e0 = fast_tanh(e0); o0 = fast_tanh(o0); e1 = fast_tanh(e1); o1 = fast_tanh(o1);
                    e2 = fast_tanh(e2); o2 = fast_tanh(o2); e3 = fast_tanh(e3); o3 = fast_tanh(o3);
                    e0 = fmaf(-(e0 * wze), e0, wze); e1 = fmaf(-(e1 * wze), e1, wze);
                    e2 = fmaf(-(e2 * wze), e2, wze); e3 = fmaf(-(e3 * wze), e3, wze);
                    o0 = fmaf(-(o0 * wzo), o0, wzo); o1 = fmaf(-(o1 * wzo), o1, wzo);
                    o2 = fmaf(-(o2 * wzo), o2, wzo); o3 = fmaf(-(o3 * wzo), o3, wzo);
                    *(float4*)&dsm[OG + (colb + 2*cp) * RPC + rowb]     = make_float4(e0,e1,e2,e3);
                    *(float4*)&dsm[OG + (colb + 2*cp + 1) * RPC + rowb] = make_float4(o0,o1,o2,o3);
                }
            }
            __syncwarp();

            // ---- layer 3 (pass 0 only): x += dt * (W3 @ h2 + b3) ----
            if (pass == 0) {
                u64 ac[4][4];
                {
                    const u64x2 b0 = *(const u64x2*)&dsm[OB3];
                    const u64x2 b1 = *(const u64x2*)&dsm[OB3 + 4];
                    #pragma unroll
                    for (int rr = 0; rr < 4; rr++) {
                        ac[rr][0] = b0.x; ac[rr][1] = b0.y;
                        ac[rr][2] = b1.x; ac[rr][3] = b1.y;
                    }
                }
                #pragma unroll 4
                for (int k = 0; k < HH; k++) {
                    const float4 av = *(const float4*)&dsm[OG + k * RPC + rowb];
                    const u64 p0 = pk2(av.x, av.x), p1 = pk2(av.y, av.y);
                    const u64 p2 = pk2(av.z, av.z), p3 = pk2(av.w, av.w);
                    const u64x2 w0 = *(const u64x2*)&dsm[OW3T + k * DD];
                    const u64x2 w1 = *(const u64x2*)&dsm[OW3T + k * DD + 4];
                    ac[0][0]=f2fma(p0,w0.x,ac[0][0]); ac[0][1]=f2fma(p0,w0.y,ac[0][1]);
                    ac[0][2]=f2fma(p0,w1.x,ac[0][2]); ac[0][3]=f2fma(p0,w1.y,ac[0][3]);
                    ac[1][0]=f2fma(p1,w0.x,ac[1][0]); ac[1][1]=f2fma(p1,w0.y,ac[1][1]);
                    ac[1][2]=f2fma(p1,w1.x,ac[1][2]); ac[1][3]=f2fma(p1,w1.y,ac[1][3]);
                    ac[2][0]=f2fma(p2,w0.x,ac[2][0]); ac[2][1]=f2fma(p2,w0.y,ac[2][1]);
                    ac[2][2]=f2fma(p2,w1.x,ac[2][2]); ac[2][3]=f2fma(p2,w1.y,ac[2][3]);
                    ac[3][0]=f2fma(p3,w0.x,ac[3][0]); ac[3][1]=f2fma(p3,w0.y,ac[3][1]);
                    ac[3][2]=f2fma(p3,w1.x,ac[3][2]); ac[3][3]=f2fma(p3,w1.y,ac[3][3]);
                }
                if (c8 == 0) {
                    float dxf[4][8];
                    #pragma unroll
                    for (int rr = 0; rr < 4; rr++) {
                        up2(ac[rr][0], dxf[rr][0], dxf[rr][1]);
                        up2(ac[rr][1], dxf[rr][2], dxf[rr][3]);
                        up2(ac[rr][2], dxf[rr][4], dxf[rr][5]);
                        up2(ac[rr][3], dxf[rr][6], dxf[rr][7]);
                    }
                    #pragma unroll
                    for (int d = 0; d < DD; d++) {
                        float4 cur = *(const float4*)&dsm[OX + d * RPC + rowb];
                        cur.x = fmaf(dt, dxf[0][d], cur.x);
                        cur.y = fmaf(dt, dxf[1][d], cur.y);
                        cur.z = fmaf(dt, dxf[2][d], cur.z);
                        cur.w = fmaf(dt, dxf[3][d], cur.w);
                        *(float4*)&dsm[OX + d * RPC + rowb] = cur;
                    }
                }
                __syncwarp();
            }
        }

        // ---- backward matvec: gh1[k] = sum_j g_a2[j] * W2[j][k]; fold into ld ----
        {
            u64 acc[4][4];
            #pragma unroll
            for (int rr = 0; rr < 4; rr++)
                #pragma unroll
                for (int jj = 0; jj < 4; jj++) acc[rr][jj] = 0ull;
            MVK(OG, OW2, 64)

            float p0 = 0.f, p1 = 0.f, p2 = 0.f, p3 = 0.f;
            #pragma unroll
            for (int cp = 0; cp < 4; cp++) {
                const int k0 = colb + 2 * cp;
                const float w1e = dsm[OW1S + k0];
                const float w1o = dsm[OW1S + k0 + 1];
                const float4 he = *(const float4*)&dsm[OH + k0 * RPC + rowb];
                const float4 ho = *(const float4*)&dsm[OH + (k0 + 1) * RPC + rowb];
                float e0,o0,e1,o1,e2,o2,e3,o3;
                up2(acc[0][cp], e0, o0); up2(acc[1][cp], e1, o1);
                up2(acc[2][cp], e2, o2); up2(acc[3][cp], e3, o3);
                float te, to;
                te = e0 * w1e; p0 += te; p0 = fmaf(-(te * he.x), he.x, p0);
                to = o0 * w1o; p0 += to; p0 = fmaf(-(to * ho.x), ho.x, p0);
                te = e1 * w1e; p1 += te; p1 = fmaf(-(te * he.y), he.y, p1);
                to = o1 * w1o; p1 += to; p1 = fmaf(-(to * ho.y), ho.y, p1);
                te = e2 * w1e; p2 += te; p2 = fmaf(-(te * he.z), he.z, p2);
                to = o2 * w1o; p2 += to; p2 = fmaf(-(to * ho.z), ho.z, p2);
                te = e3 * w1e; p3 += te; p3 = fmaf(-(te * he.w), he.w, p3);
                to = o3 * w1o; p3 += to; p3 = fmaf(-(to * ho.w), ho.w, p3);
            }
            // reduce over the 8 column-threads (lane bits 0..2)
            p0 += __shfl_xor_sync(0xffffffffu, p0, 1);
            p0 += __shfl_xor_sync(0xffffffffu, p0, 2);
            p0 += __shfl_xor_sync(0xffffffffu, p0, 4);
            p1 += __shfl_xor_sync(0xffffffffu, p1, 1);
            p1 += __shfl_xor_sync(0xffffffffu, p1, 2);
            p1 += __shfl_xor_sync(0xffffffffu, p1, 4);
            p2 += __shfl_xor_sync(0xffffffffu, p2, 1);
            p2 += __shfl_xor_sync(0xffffffffu, p2, 2);
            p2 += __shfl_xor_sync(0xffffffffu, p2, 4);
            p3 += __shfl_xor_sync(0xffffffffu, p3, 1);
            p3 += __shfl_xor_sync(0xffffffffu, p3, 2);
            p3 += __shfl_xor_sync(0xffffffffu, p3, 4);
            ldr0 = fmaf(dt, p0, ldr0);
            ldr1 = fmaf(dt, p1, ldr1);
            ldr2 = fmaf(dt, p2, ldr2);
            ldr3 = fmaf(dt, p3, ldr3);
        }
        __syncwarp();   // protect OH/OG before next step overwrites
    }

    // ---------------- output ----------------
    if (c8 == 0) {
        #pragma unroll
        for (int i2 = 0; i2 < 4; i2++) {
            const int row = base + rowb + i2;
            if (row < n) {
                float v[8];
                #pragma unroll
                for (int d = 0; d < DD; d++) v[d] = dsm[OX + d * RPC + rowb + i2];
                *(float4*)&out[row * DD]     = make_float4(v[0], v[1], v[2], v[3]);
                *(float4*)&out[row * DD + 4] = make_float4(v[4], v[5], v[6], v[7]);
            }
        }
        const int row0 = base + rowb;
        if (row0 + 3 < n) {
            *(float4*)&out[n * DD + row0] = make_float4(ldr0, ldr1, ldr2, ldr3);
        } else {
            if (row0 < n)     out[n * DD + row0]     = ldr0;
            if (row0 + 1 < n) out[n * DD + row0 + 1] = ldr1;
            if (row0 + 2 < n) out[n * DD + row0 + 2] = ldr2;
            if (row0 + 3 < n) out[n * DD + row0 + 3] = ldr3;
        }
    }
}

extern "C" void kernel_launch(void* const* d_in, const int* in_sizes, int n_in,
                              void* d_out, int out_size) {
    const float* x0 = (const float*)d_in[0];
    const float* W1 = (const float*)d_in[1];
    const float* b1 = (const float*)d_in[2];
    const float* W2 = (const float*)d_in[3];
    const float* b2 = (const float*)d_in[4];
    const float* W3 = (const float*)d_in[5];
    const float* b3 = (const float*)d_in[6];
    const int* nsp = (n_in > 7) ? (const int*)d_in[7] : nullptr;

    cudaFuncSetAttribute(cnf_kernel,
                         cudaFuncAttributeMaxDynamicSharedMemorySize, SMEM_BYTES);

    int n = in_sizes[0] / DD;
    int blocks = (n + RPC - 1) / RPC;
    cnf_kernel<<<blocks, TPB, SMEM_BYTES>>>(x0, W1, b1, W2, b2, W3, b3, nsp,
                                            (float*)d_out, n);
}

// round 15
// speedup vs baseline: 1.2593x; 1.2593x over previous
#include <cuda_runtime.h>

#define DD 8
#define HH 64
#define TPB 256
#define RPC 256   // rows per CTA (8 warps x 32 rows)

// ---- dynamic shared memory layout (float offsets; all 16B aligned) ----
#define OW1T 0        // [9][64]   W1^T ([d][j]; d==8 is t row)
#define OB1  576      // [64]
#define OW2T 640      // [64][64]  W2^T ([k][j]) forward
#define OW2  4736     // [64][64]  W2   ([j][k]) backward
#define OB2  8832     // [64]
#define OW3T 8896     // [64][8]   W3^T ([k][d])
#define OB3  9408     // [8] (+8 pad)
#define OW1S 9424     // [64] sum_{d<8} W1[k][d]
#define OW3S 9488     // [64] sum_d W3[d][j]
#define OX   9552     // [8][RPC]  x state ([d][row])
#define OH   11600    // [64][RPC] h1 state ([col][row])
#define OG   27984    // [64][RPC] h2 / g_a2 state ([col][row])
#define SMEM_FLOATS 44368
#define SMEM_BYTES  (SMEM_FLOATS * 4)   // 177472 B

typedef unsigned long long u64;
typedef ulonglong2 u64x2;

__device__ __forceinline__ u64 pk2(float a, float b) {
    u64 r; asm("mov.b64 %0, {%1,%2};" : "=l"(r) : "f"(a), "f"(b)); return r;
}
__device__ __forceinline__ void up2(u64 v, float& a, float& b) {
    asm("mov.b64 {%0,%1}, %2;" : "=f"(a), "=f"(b) : "l"(v));
}
__device__ __forceinline__ u64 f2fma(u64 a, u64 b, u64 c) {
    u64 d; asm("fma.rn.f32x2 %0, %1, %2, %3;" : "=l"(d) : "l"(a), "l"(b), "l"(c)); return d;
}
__device__ __forceinline__ u64 mul2(u64 a, u64 b) {
    u64 d; asm("mul.rn.f32x2 %0, %1, %2;" : "=l"(d) : "l"(a), "l"(b)); return d;
}
__device__ __forceinline__ u64 add2(u64 a, u64 b) {
    u64 d; asm("add.rn.f32x2 %0, %1, %2;" : "=l"(d) : "l"(a), "l"(b)); return d;
}
// tanh(x) = 1 - 2/(exp2(2*log2e*x)+1); saturates correctly, ~1e-6 rel err.
__device__ __forceinline__ float fast_tanh(float x) {
    float e; asm("ex2.approx.f32 %0, %1;" : "=f"(e) : "f"(x * 2.88539008177792681472f));
    float r; asm("rcp.approx.f32 %0, %1;" : "=f"(r) : "f"(e + 1.0f));
    return fmaf(-2.0f, r, 1.0f);
}

// 8 packed FMAs for one row-pair S against 8 packed weights
#define ACC8(RP, S) \
    acc[RP][0]=f2fma(S,w0,acc[RP][0]); acc[RP][1]=f2fma(S,w1,acc[RP][1]); \
    acc[RP][2]=f2fma(S,w2,acc[RP][2]); acc[RP][3]=f2fma(S,w3,acc[RP][3]); \
    acc[RP][4]=f2fma(S,w4,acc[RP][4]); acc[RP][5]=f2fma(S,w5,acc[RP][5]); \
    acc[RP][6]=f2fma(S,w6,acc[RP][6]); acc[RP][7]=f2fma(S,w7,acc[RP][7]);

// k-loop: state row-pairs (2x LDS.128 = 8 rows), weight scalars (2x LDS.128 = 8 cols),
// 8 pk2, 32 f2fma  ->  1:8 LDS:FMA ratio
#define MVKP(SRCOFF, WOFF, WS, CB, KBASE, KN) \
    _Pragma("unroll 4") \
    for (int k = (KBASE); k < (KBASE) + (KN); k++) { \
        const u64x2 sA = *(const u64x2*)&dsm[(SRCOFF) + k * RPC + rowb]; \
        const u64x2 sB = *(const u64x2*)&dsm[(SRCOFF) + k * RPC + rowb + 4]; \
        const float4 wa = *(const float4*)&dsm[(WOFF) + k * (WS) + (CB)]; \
        const float4 wb = *(const float4*)&dsm[(WOFF) + k * (WS) + (CB) + 4]; \
        const u64 w0 = pk2(wa.x, wa.x), w1 = pk2(wa.y, wa.y); \
        const u64 w2 = pk2(wa.z, wa.z), w3 = pk2(wa.w, wa.w); \
        const u64 w4 = pk2(wb.x, wb.x), w5 = pk2(wb.y, wb.y); \
        const u64 w6 = pk2(wb.z, wb.z), w7 = pk2(wb.w, wb.w); \
        ACC8(0, sA.x) ACC8(1, sA.y) ACC8(2, sB.x) ACC8(3, sB.y) \
    }

// init acc[rp][j] = (b_j, b_j)
#define BIAS8(BOFF) \
    { const float4 ba = *(const float4*)&dsm[(BOFF) + colb]; \
      const float4 bb = *(const float4*)&dsm[(BOFF) + colb + 4]; \
      const u64 b0=pk2(ba.x,ba.x), b1=pk2(ba.y,ba.y), b2=pk2(ba.z,ba.z), b3=pk2(ba.w,ba.w); \
      const u64 b4=pk2(bb.x,bb.x), b5=pk2(bb.y,bb.y), b6=pk2(bb.z,bb.z), b7=pk2(bb.w,bb.w); \
      _Pragma("unroll") \
      for (int rp = 0; rp < 4; rp++) { \
          acc[rp][0]=b0; acc[rp][1]=b1; acc[rp][2]=b2; acc[rp][3]=b3; \
          acc[rp][4]=b4; acc[rp][5]=b5; acc[rp][6]=b6; acc[rp][7]=b7; } }

// tanh + writeback: per col j, 8 rows -> 2 STS.128
#define WBT(OFF) \
    _Pragma("unroll") \
    for (int j = 0; j < 8; j++) { \
        float e0,o0,e1,o1,e2,o2,e3,o3; \
        up2(acc[0][j], e0,o0); up2(acc[1][j], e1,o1); \
        up2(acc[2][j], e2,o2); up2(acc[3][j], e3,o3); \
        *(float4*)&dsm[(OFF)+(colb+j)*RPC+rowb] = \
            make_float4(fast_tanh(e0),fast_tanh(o0),fast_tanh(e1),fast_tanh(o1)); \
        *(float4*)&dsm[(OFF)+(colb+j)*RPC+rowb+4] = \
            make_float4(fast_tanh(e2),fast_tanh(o2),fast_tanh(e3),fast_tanh(o3)); \
    }

__global__ void __launch_bounds__(TPB, 1)
cnf_kernel(const float* __restrict__ x0,
           const float* __restrict__ W1g,   // [64][9]
           const float* __restrict__ b1g,   // [64]
           const float* __restrict__ W2g,   // [64][64]
           const float* __restrict__ b2g,   // [64]
           const float* __restrict__ W3g,   // [8][64]
           const float* __restrict__ b3g,   // [8]
           const int*   __restrict__ nsp,
           float* __restrict__ out, int n)
{
    extern __shared__ float dsm[];
    const int tid = threadIdx.x;

    // ---------------- cooperative weight init ----------------
    for (int idx = tid; idx < HH * HH; idx += TPB) {
        int j = idx >> 6, k = idx & 63;
        float v = W2g[idx];
        dsm[OW2 + j * HH + k]  = v;   // [j][k]
        dsm[OW2T + k * HH + j] = v;   // [k][j]
    }
    for (int idx = tid; idx < HH * (DD + 1); idx += TPB) {
        int j = idx / (DD + 1), d = idx % (DD + 1);
        dsm[OW1T + d * HH + j] = W1g[idx];
    }
    for (int idx = tid; idx < HH * DD; idx += TPB) {
        int d = idx >> 6, k = idx & 63;
        dsm[OW3T + k * DD + d] = W3g[idx];
    }
    for (int idx = tid; idx < HH; idx += TPB) {
        dsm[OB1 + idx] = b1g[idx];
        dsm[OB2 + idx] = b2g[idx];
        float s1 = 0.f;
        for (int d = 0; d < DD; d++) s1 += W1g[idx * (DD + 1) + d];
        dsm[OW1S + idx] = s1;
        float s3 = 0.f;
        for (int d = 0; d < DD; d++) s3 += W3g[d * HH + idx];
        dsm[OW3S + idx] = s3;
    }
    if (tid < DD) dsm[OB3 + tid] = b3g[tid];
    if (tid >= DD && tid < 16) dsm[OB3 + tid] = 0.f;

    // ---------------- x state init ([d][row] transposed) ----------------
    const int base = blockIdx.x * RPC;
    for (int idx = tid; idx < RPC * DD; idx += TPB) {
        int rr = idx >> 3, d = idx & 7;
        int grow = base + rr;
        dsm[OX + d * RPC + rr] = (grow < n) ? x0[grow * DD + d] : 0.f;
    }
    __syncthreads();

    // warp tile: warp = 32 rows; thread = 8 rows x 8 cols
    const int lane = tid & 31;
    const int warp = tid >> 5;
    const int r4   = lane >> 3;       // 0..3
    const int c8   = lane & 7;        // 0..7
    const int rowb = warp * 32 + r4 * 8;   // first of this thread's 8 rows
    const int colb = c8 * 8;               // first of this thread's 8 cols

    const int nsteps = nsp ? *nsp : 100;
    const float dt = 1.0f / (float)nsteps;
    const u64 dtp = pk2(dt, dt);
    const u64 one2 = pk2(1.0f, 1.0f);
    const u64 none2 = pk2(-1.0f, -1.0f);

    u64 ldr[4] = {0ull, 0ull, 0ull, 0ull};   // packed log-det accum (8 rows)

    #pragma unroll 1
    for (int i = 0; i < nsteps; i++) {
        const float t = (float)i * dt;

        #pragma unroll 1
        for (int pass = 0; pass < 2; pass++) {
            // ---- layer 1: OH = tanh(W1 @ [x; t] + b1) ----
            {
                u64 acc[4][8];
                BIAS8(OB1)
                MVKP(OX, OW1T, HH, colb, 0, 8)
                {   // t row (d == 8)
                    const float4 wa = *(const float4*)&dsm[OW1T + 8 * HH + colb];
                    const float4 wb = *(const float4*)&dsm[OW1T + 8 * HH + colb + 4];
                    const u64 w0 = pk2(wa.x, wa.x), w1 = pk2(wa.y, wa.y);
                    const u64 w2 = pk2(wa.z, wa.z), w3 = pk2(wa.w, wa.w);
                    const u64 w4 = pk2(wb.x, wb.x), w5 = pk2(wb.y, wb.y);
                    const u64 w6 = pk2(wb.z, wb.z), w7 = pk2(wb.w, wb.w);
                    const u64 pt = pk2(t, t);
                    ACC8(0, pt) ACC8(1, pt) ACC8(2, pt) ACC8(3, pt)
                }
                WBT(OH)
            }
            __syncwarp();

            // ---- layer 2 ----
            if (pass == 0) {
                u64 acc[4][8];
                BIAS8(OB2)
                MVKP(OH, OW2T, HH, colb, 0, 64)
                WBT(OG)
            } else {
                // fused: g = tanh(.); OG = w3s * (1 - g^2)
                u64 acc[4][8];
                BIAS8(OB2)
                MVKP(OH, OW2T, HH, colb, 0, 64)
                #pragma unroll
                for (int j = 0; j < 8; j++) {
                    const float wz = dsm[OW3S + colb + j];
                    float e0,o0,e1,o1,e2,o2,e3,o3;
                    up2(acc[0][j], e0,o0); up2(acc[1][j], e1,o1);
                    up2(acc[2][j], e2,o2); up2(acc[3][j], e3,o3);
                    e0=fast_tanh(e0); o0=fast_tanh(o0); e1=fast_tanh(e1); o1=fast_tanh(o1);
                    e2=fast_tanh(e2); o2=fast_tanh(o2); e3=fast_tanh(e3); o3=fast_tanh(o3);
                    e0=fmaf(-(e0*wz), e0, wz); o0=fmaf(-(o0*wz), o0, wz);
                    e1=fmaf(-(e1*wz), e1, wz); o1=fmaf(-(o1*wz), o1, wz);
                    e2=fmaf(-(e2*wz), e2, wz); o2=fmaf(-(o2*wz), o2, wz);
                    e3=fmaf(-(e3*wz), e3, wz); o3=fmaf(-(o3*wz), o3, wz);
                    *(float4*)&dsm[OG+(colb+j)*RPC+rowb]   = make_float4(e0,o0,e1,o1);
                    *(float4*)&dsm[OG+(colb+j)*RPC+rowb+4] = make_float4(e2,o2,e3,o3);
                }
            }
            __syncwarp();

            // ---- layer 3 (pass 0 only): x += dt * (W3 @ h2 + b3), split-k ----
            if (pass == 0) {
                u64 acc[4][8];
                #pragma unroll
                for (int rp = 0; rp < 4; rp++)
                    #pragma unroll
                    for (int j = 0; j < 8; j++) acc[rp][j] = 0ull;
                // this thread's k-slice: [c8*8, c8*8+8), cols 0..7 (CB = 0)
                MVKP(OG, OW3T, DD, 0, c8 * 8, 8)
                // reduce partial sums across the 8 c8-lanes
                #pragma unroll
                for (int d = 1; d <= 4; d <<= 1) {
                    #pragma unroll
                    for (int rp = 0; rp < 4; rp++)
                        #pragma unroll
                        for (int j = 0; j < 8; j++)
                            acc[rp][j] = add2(acc[rp][j],
                                __shfl_xor_sync(0xffffffffu, acc[rp][j], d));
                }
                if (c8 == 0) {
                    const float4 b3a = *(const float4*)&dsm[OB3];
                    const float4 b3b = *(const float4*)&dsm[OB3 + 4];
                    const float bv[8] = {b3a.x,b3a.y,b3a.z,b3a.w,b3b.x,b3b.y,b3b.z,b3b.w};
                    #pragma unroll
                    for (int d = 0; d < 8; d++) {
                        const u64 bp = pk2(bv[d], bv[d]);
                        u64x2 xA = *(u64x2*)&dsm[OX + d * RPC + rowb];
                        u64x2 xB = *(u64x2*)&dsm[OX + d * RPC + rowb + 4];
                        xA.x = f2fma(add2(acc[0][d], bp), dtp, xA.x);
                        xA.y = f2fma(add2(acc[1][d], bp), dtp, xA.y);
                        xB.x = f2fma(add2(acc[2][d], bp), dtp, xB.x);
                        xB.y = f2fma(add2(acc[3][d], bp), dtp, xB.y);
                        *(u64x2*)&dsm[OX + d * RPC + rowb] = xA;
                        *(u64x2*)&dsm[OX + d * RPC + rowb + 4] = xB;
                    }
                }
                __syncwarp();
            }
        }

        // ---- backward: gh1[k] = sum_j g_a2[j] * W2[j][k]; fold into ld ----
        {
            u64 acc[4][8];
            #pragma unroll
            for (int rp = 0; rp < 4; rp++)
                #pragma unroll
                for (int j = 0; j < 8; j++) acc[rp][j] = 0ull;
            MVKP(OG, OW2, HH, colb, 0, 64)

            u64 ldp[4] = {0ull, 0ull, 0ull, 0ull};
            #pragma unroll
            for (int j = 0; j < 8; j++) {
                const int k0 = colb + j;
                const float ws = dsm[OW1S + k0];
                const u64 wp = pk2(ws, ws);
                const u64x2 hA = *(const u64x2*)&dsm[OH + k0 * RPC + rowb];
                const u64x2 hB = *(const u64x2*)&dsm[OH + k0 * RPC + rowb + 4];
                #define FOLD(RP, H) { \
                    const u64 tt = mul2(acc[RP][j], wp); \
                    const u64 hh = mul2(H, H); \
                    const u64 om = f2fma(hh, none2, one2); \
                    ldp[RP] = f2fma(tt, om, ldp[RP]); }
                FOLD(0, hA.x) FOLD(1, hA.y) FOLD(2, hB.x) FOLD(3, hB.y)
                #undef FOLD
            }
            // reduce over the 8 c8-lanes (each handled 8 distinct k columns)
            #pragma unroll
            for (int d = 1; d <= 4; d <<= 1) {
                #pragma unroll
                for (int rp = 0; rp < 4; rp++)
                    ldp[rp] = add2(ldp[rp], __shfl_xor_sync(0xffffffffu, ldp[rp], d));
            }
            #pragma unroll
            for (int rp = 0; rp < 4; rp++)
                ldr[rp] = f2fma(ldp[rp], dtp, ldr[rp]);
        }
        __syncwarp();   // protect OH/OG before next step overwrites
    }

    // ---------------- output ----------------
    if (c8 == 0) {
        #pragma unroll
        for (int rr = 0; rr < 8; rr++) {
            const int row = base + rowb + rr;
            if (row < n) {
                float v[8];
                #pragma unroll
                for (int d = 0; d < 8; d++) v[d] = dsm[OX + d * RPC + rowb + rr];
                *(float4*)&out[row * DD]     = make_float4(v[0], v[1], v[2], v[3]);
                *(float4*)&out[row * DD + 4] = make_float4(v[4], v[5], v[6], v[7]);
            }
        }
        float lv[8];
        up2(ldr[0], lv[0], lv[1]); up2(ldr[1], lv[2], lv[3]);
        up2(ldr[2], lv[4], lv[5]); up2(ldr[3], lv[6], lv[7]);
        const int row0 = base + rowb;
        if (row0 + 7 < n) {
            *(float4*)&out[n * DD + row0]     = make_float4(lv[0], lv[1], lv[2], lv[3]);
            *(float4*)&out[n * DD + row0 + 4] = make_float4(lv[4], lv[5], lv[6], lv[7]);
        } else {
            #pragma unroll
            for (int rr = 0; rr < 8; rr++)
                if (row0 + rr < n) out[n * DD + row0 + rr] = lv[rr];
        }
    }
}

extern "C" void kernel_launch(void* const* d_in, const int* in_sizes, int n_in,
                              void* d_out, int out_size) {
    const float* x0 = (const float*)d_in[0];
    const float* W1 = (const float*)d_in[1];
    const float* b1 = (const float*)d_in[2];
    const float* W2 = (const float*)d_in[3];
    const float* b2 = (const float*)d_in[4];
    const float* W3 = (const float*)d_in[5];
    const float* b3 = (const float*)d_in[6];
    const int* nsp = (n_in > 7) ? (const int*)d_in[7] : nullptr;

    cudaFuncSetAttribute(cnf_kernel,
                         cudaFuncAttributeMaxDynamicSharedMemorySize, SMEM_BYTES);

    int n = in_sizes[0] / DD;
    int blocks = (n + RPC - 1) / RPC;
    cnf_kernel<<<blocks, TPB, SMEM_BYTES>>>(x0, W1, b1, W2, b2, W3, b3, nsp,
                                            (float*)d_out, n);
}

// round 16
// speedup vs baseline: 1.3644x; 1.0835x over previous
#include <cuda_runtime.h>

#define DD 8
#define HH 64
#define TPB 224
#define RPC 224   // rows per CTA (7 warps x 32 rows)

// ---- dynamic shared memory layout (float offsets; all 16B aligned) ----
#define OW1T 0        // [9][64]   W1^T ([d][j]; d==8 is t row)
#define OB1  576      // [64]
#define OW2T 640      // [64][64]  W2^T ([k][j]) forward
#define OW2  4736     // [64][64]  W2   ([j][k]) backward
#define OB2  8832     // [64]
#define OW3T 8896     // [64][8]   W3^T ([k][d])
#define OB3  9408     // [8] (+8 pad)
#define OW1S 9424     // [64] sum_{d<8} W1[k][d]
#define OW3S 9488     // [64] sum_d W3[d][j]
#define OX   9552     // [8][RPC]  x state ([d][row])
#define OH   11344    // [64][RPC] h1 state ([col][row])
#define OG   25680    // [64][RPC] h2 / g_a2 state ([col][row])
#define SMEM_FLOATS 40016
#define SMEM_BYTES  (SMEM_FLOATS * 4)   // 160064 B

typedef unsigned long long u64;
typedef ulonglong2 u64x2;

__device__ __forceinline__ u64 pk2(float a, float b) {
    u64 r; asm("mov.b64 %0, {%1,%2};" : "=l"(r) : "f"(a), "f"(b)); return r;
}
__device__ __forceinline__ void up2(u64 v, float& a, float& b) {
    asm("mov.b64 {%0,%1}, %2;" : "=f"(a), "=f"(b) : "l"(v));
}
__device__ __forceinline__ u64 f2fma(u64 a, u64 b, u64 c) {
    u64 d; asm("fma.rn.f32x2 %0, %1, %2, %3;" : "=l"(d) : "l"(a), "l"(b), "l"(c)); return d;
}
__device__ __forceinline__ u64 mul2(u64 a, u64 b) {
    u64 d; asm("mul.rn.f32x2 %0, %1, %2;" : "=l"(d) : "l"(a), "l"(b)); return d;
}
__device__ __forceinline__ u64 add2(u64 a, u64 b) {
    u64 d; asm("add.rn.f32x2 %0, %1, %2;" : "=l"(d) : "l"(a), "l"(b)); return d;
}
// tanh(x) = 1 - 2/(exp2(2*log2e*x)+1); saturates correctly, ~1e-6 rel err.
__device__ __forceinline__ float fast_tanh(float x) {
    float e; asm("ex2.approx.f32 %0, %1;" : "=f"(e) : "f"(x * 2.88539008177792681472f));
    float r; asm("rcp.approx.f32 %0, %1;" : "=f"(r) : "f"(e + 1.0f));
    return fmaf(-2.0f, r, 1.0f);
}

// 8 packed FMAs for one row-pair S against 8 packed weights
#define ACC8(RP, S) \
    acc[RP][0]=f2fma(S,w0,acc[RP][0]); acc[RP][1]=f2fma(S,w1,acc[RP][1]); \
    acc[RP][2]=f2fma(S,w2,acc[RP][2]); acc[RP][3]=f2fma(S,w3,acc[RP][3]); \
    acc[RP][4]=f2fma(S,w4,acc[RP][4]); acc[RP][5]=f2fma(S,w5,acc[RP][5]); \
    acc[RP][6]=f2fma(S,w6,acc[RP][6]); acc[RP][7]=f2fma(S,w7,acc[RP][7]);

// k-loop: state row-pairs (2x LDS.128 = 8 rows), weight scalars (2x LDS.128 = 8 cols),
// 8 pk2, 32 f2fma
#define MVKP(SRCOFF, WOFF, WS, CB, KBASE, KN) \
    _Pragma("unroll 4") \
    for (int k = (KBASE); k < (KBASE) + (KN); k++) { \
        const u64x2 sA = *(const u64x2*)&dsm[(SRCOFF) + k * RPC + rowb]; \
        const u64x2 sB = *(const u64x2*)&dsm[(SRCOFF) + k * RPC + rowb + 4]; \
        const float4 wa = *(const float4*)&dsm[(WOFF) + k * (WS) + (CB)]; \
        const float4 wb = *(const float4*)&dsm[(WOFF) + k * (WS) + (CB) + 4]; \
        const u64 w0 = pk2(wa.x, wa.x), w1 = pk2(wa.y, wa.y); \
        const u64 w2 = pk2(wa.z, wa.z), w3 = pk2(wa.w, wa.w); \
        const u64 w4 = pk2(wb.x, wb.x), w5 = pk2(wb.y, wb.y); \
        const u64 w6 = pk2(wb.z, wb.z), w7 = pk2(wb.w, wb.w); \
        ACC8(0, sA.x) ACC8(1, sA.y) ACC8(2, sB.x) ACC8(3, sB.y) \
    }

// init acc[rp][j] = (b_j, b_j)
#define BIAS8(BOFF) \
    { const float4 ba = *(const float4*)&dsm[(BOFF) + colb]; \
      const float4 bb = *(const float4*)&dsm[(BOFF) + colb + 4]; \
      const u64 b0=pk2(ba.x,ba.x), b1=pk2(ba.y,ba.y), b2=pk2(ba.z,ba.z), b3=pk2(ba.w,ba.w); \
      const u64 b4=pk2(bb.x,bb.x), b5=pk2(bb.y,bb.y), b6=pk2(bb.z,bb.z), b7=pk2(bb.w,bb.w); \
      _Pragma("unroll") \
      for (int rp = 0; rp < 4; rp++) { \
          acc[rp][0]=b0; acc[rp][1]=b1; acc[rp][2]=b2; acc[rp][3]=b3; \
          acc[rp][4]=b4; acc[rp][5]=b5; acc[rp][6]=b6; acc[rp][7]=b7; } }

// tanh + writeback: per col j, 8 rows -> 2 STS.128
#define WBT(OFF) \
    _Pragma("unroll") \
    for (int j = 0; j < 8; j++) { \
        float e0,o0,e1,o1,e2,o2,e3,o3; \
        up2(acc[0][j], e0,o0); up2(acc[1][j], e1,o1); \
        up2(acc[2][j], e2,o2); up2(acc[3][j], e3,o3); \
        *(float4*)&dsm[(OFF)+(colb+j)*RPC+rowb] = \
            make_float4(fast_tanh(e0),fast_tanh(o0),fast_tanh(e1),fast_tanh(o1)); \
        *(float4*)&dsm[(OFF)+(colb+j)*RPC+rowb+4] = \
            make_float4(fast_tanh(e2),fast_tanh(o2),fast_tanh(e3),fast_tanh(o3)); \
    }

__global__ void __launch_bounds__(TPB, 1)
cnf_kernel(const float* __restrict__ x0,
           const float* __restrict__ W1g,   // [64][9]
           const float* __restrict__ b1g,   // [64]
           const float* __restrict__ W2g,   // [64][64]
           const float* __restrict__ b2g,   // [64]
           const float* __restrict__ W3g,   // [8][64]
           const float* __restrict__ b3g,   // [8]
           const int*   __restrict__ nsp,
           float* __restrict__ out, int n)
{
    extern __shared__ float dsm[];
    const int tid = threadIdx.x;

    // ---------------- cooperative weight init ----------------
    for (int idx = tid; idx < HH * HH; idx += TPB) {
        int j = idx >> 6, k = idx & 63;
        float v = W2g[idx];
        dsm[OW2 + j * HH + k]  = v;   // [j][k]
        dsm[OW2T + k * HH + j] = v;   // [k][j]
    }
    for (int idx = tid; idx < HH * (DD + 1); idx += TPB) {
        int j = idx / (DD + 1), d = idx % (DD + 1);
        dsm[OW1T + d * HH + j] = W1g[idx];
    }
    for (int idx = tid; idx < HH * DD; idx += TPB) {
        int d = idx >> 6, k = idx & 63;
        dsm[OW3T + k * DD + d] = W3g[idx];
    }
    for (int idx = tid; idx < HH; idx += TPB) {
        dsm[OB1 + idx] = b1g[idx];
        dsm[OB2 + idx] = b2g[idx];
        float s1 = 0.f;
        for (int d = 0; d < DD; d++) s1 += W1g[idx * (DD + 1) + d];
        dsm[OW1S + idx] = s1;
        float s3 = 0.f;
        for (int d = 0; d < DD; d++) s3 += W3g[d * HH + idx];
        dsm[OW3S + idx] = s3;
    }
    if (tid < DD) dsm[OB3 + tid] = b3g[tid];
    if (tid >= DD && tid < 16) dsm[OB3 + tid] = 0.f;

    // ---------------- x state init ([d][row] transposed) ----------------
    const int base = blockIdx.x * RPC;
    for (int idx = tid; idx < RPC * DD; idx += TPB) {
        int rr = idx >> 3, d = idx & 7;
        int grow = base + rr;
        dsm[OX + d * RPC + rr] = (grow < n) ? x0[grow * DD + d] : 0.f;
    }
    __syncthreads();

    // warp tile: warp = 32 rows; thread = 8 rows x 8 cols
    const int lane = tid & 31;
    const int warp = tid >> 5;
    const int r4   = lane >> 3;       // 0..3
    const int c8   = lane & 7;        // 0..7
    const int rowb = warp * 32 + r4 * 8;   // first of this thread's 8 rows
    const int colb = c8 * 8;               // first of this thread's 8 cols

    const int nsteps = nsp ? *nsp : 100;
    const float dt = 1.0f / (float)nsteps;
    const u64 dtp = pk2(dt, dt);
    const u64 one2 = pk2(1.0f, 1.0f);
    const u64 none2 = pk2(-1.0f, -1.0f);

    u64 ldr[4] = {0ull, 0ull, 0ull, 0ull};   // packed log-det accum (8 rows)

    #pragma unroll 1
    for (int i = 0; i < nsteps; i++) {
        const float t = (float)i * dt;

        #pragma unroll 1
        for (int pass = 0; pass < 2; pass++) {
            // ---- layer 1: OH = tanh(W1 @ [x; t] + b1) ----
            {
                u64 acc[4][8];
                BIAS8(OB1)
                MVKP(OX, OW1T, HH, colb, 0, 8)
                {   // t row (d == 8)
                    const float4 wa = *(const float4*)&dsm[OW1T + 8 * HH + colb];
                    const float4 wb = *(const float4*)&dsm[OW1T + 8 * HH + colb + 4];
                    const u64 w0 = pk2(wa.x, wa.x), w1 = pk2(wa.y, wa.y);
                    const u64 w2 = pk2(wa.z, wa.z), w3 = pk2(wa.w, wa.w);
                    const u64 w4 = pk2(wb.x, wb.x), w5 = pk2(wb.y, wb.y);
                    const u64 w6 = pk2(wb.z, wb.z), w7 = pk2(wb.w, wb.w);
                    const u64 pt = pk2(t, t);
                    ACC8(0, pt) ACC8(1, pt) ACC8(2, pt) ACC8(3, pt)
                }
                WBT(OH)
            }
            __syncwarp();

            // ---- layer 2 ----
            if (pass == 0) {
                u64 acc[4][8];
                BIAS8(OB2)
                MVKP(OH, OW2T, HH, colb, 0, 64)
                WBT(OG)
            } else {
                // fused: g = tanh(.); OG = w3s * (1 - g^2)
                u64 acc[4][8];
                BIAS8(OB2)
                MVKP(OH, OW2T, HH, colb, 0, 64)
                #pragma unroll
                for (int j = 0; j < 8; j++) {
                    const float wz = dsm[OW3S + colb + j];
                    float e0,o0,e1,o1,e2,o2,e3,o3;
                    up2(acc[0][j], e0,o0); up2(acc[1][j], e1,o1);
                    up2(acc[2][j], e2,o2); up2(acc[3][j], e3,o3);
                    e0=fast_tanh(e0); o0=fast_tanh(o0); e1=fast_tanh(e1); o1=fast_tanh(o1);
                    e2=fast_tanh(e2); o2=fast_tanh(o2); e3=fast_tanh(e3); o3=fast_tanh(o3);
                    e0=fmaf(-(e0*wz), e0, wz); o0=fmaf(-(o0*wz), o0, wz);
                    e1=fmaf(-(e1*wz), e1, wz); o1=fmaf(-(o1*wz), o1, wz);
                    e2=fmaf(-(e2*wz), e2, wz); o2=fmaf(-(o2*wz), o2, wz);
                    e3=fmaf(-(e3*wz), e3, wz); o3=fmaf(-(o3*wz), o3, wz);
                    *(float4*)&dsm[OG+(colb+j)*RPC+rowb]   = make_float4(e0,o0,e1,o1);
                    *(float4*)&dsm[OG+(colb+j)*RPC+rowb+4] = make_float4(e2,o2,e3,o3);
                }
            }
            __syncwarp();

            // ---- layer 3 (pass 0 only): x += dt * (W3 @ h2 + b3), split-k ----
            if (pass == 0) {
                u64 acc[4][8];
                #pragma unroll
                for (int rp = 0; rp < 4; rp++)
                    #pragma unroll
                    for (int j = 0; j < 8; j++) acc[rp][j] = 0ull;
                // this thread's k-slice: [c8*8, c8*8+8), cols 0..7 (CB = 0)
                MVKP(OG, OW3T, DD, 0, c8 * 8, 8)
                // reduce partial sums across the 8 c8-lanes
                #pragma unroll
                for (int d = 1; d <= 4; d <<= 1) {
                    #pragma unroll
                    for (int rp = 0; rp < 4; rp++)
                        #pragma unroll
                        for (int j = 0; j < 8; j++)
                            acc[rp][j] = add2(acc[rp][j],
                                __shfl_xor_sync(0xffffffffu, acc[rp][j], d));
                }
                if (c8 == 0) {
                    const float4 b3a = *(const float4*)&dsm[OB3];
                    const float4 b3b = *(const float4*)&dsm[OB3 + 4];
                    const float bv[8] = {b3a.x,b3a.y,b3a.z,b3a.w,b3b.x,b3b.y,b3b.z,b3b.w};
                    #pragma unroll
                    for (int d = 0; d < 8; d++) {
                        const u64 bp = pk2(bv[d], bv[d]);
                        u64x2 xA = *(u64x2*)&dsm[OX + d * RPC + rowb];
                        u64x2 xB = *(u64x2*)&dsm[OX + d * RPC + rowb + 4];
                        xA.x = f2fma(add2(acc[0][d], bp), dtp, xA.x);
                        xA.y = f2fma(add2(acc[1][d], bp), dtp, xA.y);
                        xB.x = f2fma(add2(acc[2][d], bp), dtp, xB.x);
                        xB.y = f2fma(add2(acc[3][d], bp), dtp, xB.y);
                        *(u64x2*)&dsm[OX + d * RPC + rowb] = xA;
                        *(u64x2*)&dsm[OX + d * RPC + rowb + 4] = xB;
                    }
                }
                __syncwarp();
            }
        }

        // ---- backward: gh1[k] = sum_j g_a2[j] * W2[j][k]; fold into ld ----
        {
            u64 acc[4][8];
            #pragma unroll
            for (int rp = 0; rp < 4; rp++)
                #pragma unroll
                for (int j = 0; j < 8; j++) acc[rp][j] = 0ull;
            MVKP(OG, OW2, HH, colb, 0, 64)

            u64 ldp[4] = {0ull, 0ull, 0ull, 0ull};
            #pragma unroll
            for (int j = 0; j < 8; j++) {
                const int k0 = colb + j;
                const float ws = dsm[OW1S + k0];
                const u64 wp = pk2(ws, ws);
                const u64x2 hA = *(const u64x2*)&dsm[OH + k0 * RPC + rowb];
                const u64x2 hB = *(const u64x2*)&dsm[OH + k0 * RPC + rowb + 4];
                #define FOLD(RP, H) { \
                    const u64 tt = mul2(acc[RP][j], wp); \
                    const u64 hh = mul2(H, H); \
                    const u64 om = f2fma(hh, none2, one2); \
                    ldp[RP] = f2fma(tt, om, ldp[RP]); }
                FOLD(0, hA.x) FOLD(1, hA.y) FOLD(2, hB.x) FOLD(3, hB.y)
                #undef FOLD
            }
            // reduce over the 8 c8-lanes (each handled 8 distinct k columns)
            #pragma unroll
            for (int d = 1; d <= 4; d <<= 1) {
                #pragma unroll
                for (int rp = 0; rp < 4; rp++)
                    ldp[rp] = add2(ldp[rp], __shfl_xor_sync(0xffffffffu, ldp[rp], d));
            }
            #pragma unroll
            for (int rp = 0; rp < 4; rp++)
                ldr[rp] = f2fma(ldp[rp], dtp, ldr[rp]);
        }
        __syncwarp();   // protect OH/OG before next step overwrites
    }

    // ---------------- output ----------------
    if (c8 == 0) {
        #pragma unroll
        for (int rr = 0; rr < 8; rr++) {
            const int row = base + rowb + rr;
            if (row < n) {
                float v[8];
                #pragma unroll
                for (int d = 0; d < 8; d++) v[d] = dsm[OX + d * RPC + rowb + rr];
                *(float4*)&out[row * DD]     = make_float4(v[0], v[1], v[2], v[3]);
                *(float4*)&out[row * DD + 4] = make_float4(v[4], v[5], v[6], v[7]);
            }
        }
        float lv[8];
        up2(ldr[0], lv[0], lv[1]); up2(ldr[1], lv[2], lv[3]);
        up2(ldr[2], lv[4], lv[5]); up2(ldr[3], lv[6], lv[7]);
        const int row0 = base + rowb;
        if (row0 + 7 < n) {
            *(float4*)&out[n * DD + row0]     = make_float4(lv[0], lv[1], lv[2], lv[3]);
            *(float4*)&out[n * DD + row0 + 4] = make_float4(lv[4], lv[5], lv[6], lv[7]);
        } else {
            #pragma unroll
            for (int rr = 0; rr < 8; rr++)
                if (row0 + rr < n) out[n * DD + row0 + rr] = lv[rr];
        }
    }
}

extern "C" void kernel_launch(void* const* d_in, const int* in_sizes, int n_in,
                              void* d_out, int out_size) {
    const float* x0 = (const float*)d_in[0];
    const float* W1 = (const float*)d_in[1];
    const float* b1 = (const float*)d_in[2];
    const float* W2 = (const float*)d_in[3];
    const float* b2 = (const float*)d_in[4];
    const float* W3 = (const float*)d_in[5];
    const float* b3 = (const float*)d_in[6];
    const int* nsp = (n_in > 7) ? (const int*)d_in[7] : nullptr;

    cudaFuncSetAttribute(cnf_kernel,
                         cudaFuncAttributeMaxDynamicSharedMemorySize, SMEM_BYTES);

    int n = in_sizes[0] / DD;
    int blocks = (n + RPC - 1) / RPC;   // 147 for n=32768 -> one wave on 147 SMs
    cnf_kernel<<<blocks, TPB, SMEM_BYTES>>>(x0, W1, b1, W2, b2, W3, b3, nsp,
                                            (float*)d_out, n);
}

// round 17
// speedup vs baseline: 4.1383x; 3.0331x over previous
#include <cuda_runtime.h>

#define DD 8
#define HH 64
#define TPB 224
#define RPC 224   // rows per CTA (7 warps x 32 rows)

// ---- dynamic shared memory layout (float offsets) ----
// strides: 68 for 64-wide arrays (68%32=4 -> conflict-free frags), 12 for 8-wide
#define PW1   0       // [64][12]  W1 cols 0..7, tf32   (B for L1: [n=j][k=d])
#define W1C8  768     // [64]      W1[:,8] fp32 (t column)
#define B1    832     // [64]
#define B2    896     // [64]
#define B3    960     // [8] (+8 pad)
#define W1S   976     // [64] sum_{d<8} W1[k][d]
#define W3S   1040    // [64] sum_d W3[d][j]
#define PW3   1104    // [8][68]   W3 row-major tf32    (B for L3: [n=d][k])
#define PW2F  1648    // [64][68]  W2 row-major tf32    (B fwd:   [n=j][k])
#define PW2B  6000    // [64][68]  W2^T tf32            (B bwd:   [n=k'][j])
#define OXF   10352   // [224][8]  x master fp32, row-major
#define OXT   12144   // [224][12] x tf32 copy (A for L1)
#define OH    14832   // [224][68] h1 tf32 (A for L2 / bwd fold)
#define OG    30064   // [224][68] h2 / ga2 tf32 (A for L3, bwd)
#define SMEM_FLOATS 45296
#define SMEM_BYTES  (SMEM_FLOATS * 4)   // 181184 B

__device__ __forceinline__ float tf32f(float f) {
    unsigned u; asm("cvt.rna.tf32.f32 %0, %1;" : "=r"(u) : "f"(f));
    return __uint_as_float(u);
}
// tanh(x) = 1 - 2/(exp2(2*log2e*x)+1); saturates correctly, ~1e-6 rel err.
__device__ __forceinline__ float fast_tanh(float x) {
    float e; asm("ex2.approx.f32 %0, %1;" : "=f"(e) : "f"(x * 2.88539008177792681472f));
    float r; asm("rcp.approx.f32 %0, %1;" : "=f"(r) : "f"(e + 1.0f));
    return fmaf(-2.0f, r, 1.0f);
}

__device__ __forceinline__ void mma8(float c[4], const unsigned a[4], const unsigned b[2]) {
    asm volatile(
        "mma.sync.aligned.m16n8k8.row.col.f32.tf32.tf32.f32 "
        "{%0,%1,%2,%3}, {%4,%5,%6,%7}, {%8,%9}, {%0,%1,%2,%3};"
        : "+f"(c[0]), "+f"(c[1]), "+f"(c[2]), "+f"(c[3])
        : "r"(a[0]), "r"(a[1]), "r"(a[2]), "r"(a[3]), "r"(b[0]), "r"(b[1]));
}

// A fragment (16x8 row-major): a0=(g,t4) a1=(g+8,t4) a2=(g,t4+4) a3=(g+8,t4+4)
#define LDA(arr, AOFF, AS, RB, K0) { \
    const int _r0 = ((RB) + g) * (AS), _r1 = ((RB) + 8 + g) * (AS); \
    arr[0] = __float_as_uint(dsm[(AOFF) + _r0 + (K0) + t4]); \
    arr[1] = __float_as_uint(dsm[(AOFF) + _r1 + (K0) + t4]); \
    arr[2] = __float_as_uint(dsm[(AOFF) + _r0 + (K0) + t4 + 4]); \
    arr[3] = __float_as_uint(dsm[(AOFF) + _r1 + (K0) + t4 + 4]); }

// B fragment (8x8): b0=(k=t4,n=g) b1=(k=t4+4,n=g); array stored [n][k]
#define LDB(arr, BOFF, BS, N0, K0) { \
    const int _b = (BOFF) + ((N0) + g) * (BS) + (K0) + t4; \
    arr[0] = __float_as_uint(dsm[_b]); \
    arr[1] = __float_as_uint(dsm[_b + 4]); }

// C fragment (16x8): c0=(g,2t4) c1=(g,2t4+1) c2=(g+8,2t4) c3=(g+8,2t4+1)
#define BIAS_INIT(BOFF) \
    _Pragma("unroll") \
    for (int nt = 0; nt < 8; nt++) { \
        const float2 bp = *(const float2*)&dsm[(BOFF) + nt * 8 + 2 * t4]; \
        c0[nt][0] = bp.x; c0[nt][1] = bp.y; c0[nt][2] = bp.x; c0[nt][3] = bp.y; \
        c1[nt][0] = bp.x; c1[nt][1] = bp.y; c1[nt][2] = bp.x; c1[nt][3] = bp.y; }

#define GEMM64(AOFF, BOFF) \
    _Pragma("unroll 2") \
    for (int k0 = 0; k0 < 64; k0 += 8) { \
        unsigned aa[4], ab[4]; \
        LDA(aa, AOFF, 68, wrow, k0) \
        LDA(ab, AOFF, 68, wrow + 16, k0) \
        _Pragma("unroll") \
        for (int nt = 0; nt < 8; nt++) { \
            unsigned bb[2]; \
            LDB(bb, BOFF, 68, nt * 8, k0) \
            mma8(c0[nt], aa, bb); \
            mma8(c1[nt], ab, bb); \
        } \
    }

#define ST2T(DOFF, ROW, COL, VA, VB) \
    *(float2*)&dsm[(DOFF) + (ROW) * 68 + (COL)] = make_float2(tf32f(VA), tf32f(VB));

#define EPI_TANH(DOFF) \
    _Pragma("unroll") \
    for (int nt = 0; nt < 8; nt++) { \
        const int cc = nt * 8 + 2 * t4; \
        ST2T(DOFF, wrow + g,      cc, fast_tanh(c0[nt][0]), fast_tanh(c0[nt][1])) \
        ST2T(DOFF, wrow + 8 + g,  cc, fast_tanh(c0[nt][2]), fast_tanh(c0[nt][3])) \
        ST2T(DOFF, wrow + 16 + g, cc, fast_tanh(c1[nt][0]), fast_tanh(c1[nt][1])) \
        ST2T(DOFF, wrow + 24 + g, cc, fast_tanh(c1[nt][2]), fast_tanh(c1[nt][3])) \
    }

// ga2 = w3s * (1 - tanh(a2)^2)
#define GA2ST(ROW, COL, VA, VB, WZ) { \
    float _a = fast_tanh(VA), _b = fast_tanh(VB); \
    _a = fmaf(-(_a * (WZ).x), _a, (WZ).x); \
    _b = fmaf(-(_b * (WZ).y), _b, (WZ).y); \
    ST2T(OG, ROW, COL, _a, _b) }

__global__ void __launch_bounds__(TPB, 1)
cnf_kernel(const float* __restrict__ x0,
           const float* __restrict__ W1g,   // [64][9]
           const float* __restrict__ b1g,   // [64]
           const float* __restrict__ W2g,   // [64][64]
           const float* __restrict__ b2g,   // [64]
           const float* __restrict__ W3g,   // [8][64]
           const float* __restrict__ b3g,   // [8]
           const int*   __restrict__ nsp,
           float* __restrict__ out, int n)
{
    extern __shared__ float dsm[];
    const int tid = threadIdx.x;

    // ---------------- weight init (tf32 pre-converted) ----------------
    for (int idx = tid; idx < HH * HH; idx += TPB) {
        int j = idx >> 6, k = idx & 63;
        float v = tf32f(W2g[idx]);
        dsm[PW2F + j * 68 + k] = v;   // [n=j][k]
        dsm[PW2B + k * 68 + j] = v;   // [n=k'][j]
    }
    for (int idx = tid; idx < HH * DD; idx += TPB) {
        int j = idx >> 3, d = idx & 7;
        dsm[PW1 + j * 12 + d] = tf32f(W1g[j * (DD + 1) + d]);
    }
    for (int idx = tid; idx < DD * HH; idx += TPB) {
        int d = idx >> 6, k = idx & 63;
        dsm[PW3 + d * 68 + k] = tf32f(W3g[idx]);
    }
    for (int idx = tid; idx < HH; idx += TPB) {
        dsm[W1C8 + idx] = W1g[idx * (DD + 1) + DD];
        dsm[B1 + idx] = b1g[idx];
        dsm[B2 + idx] = b2g[idx];
        float s1 = 0.f;
        for (int d = 0; d < DD; d++) s1 += W1g[idx * (DD + 1) + d];
        dsm[W1S + idx] = s1;
        float s3 = 0.f;
        for (int d = 0; d < DD; d++) s3 += W3g[d * HH + idx];
        dsm[W3S + idx] = s3;
    }
    if (tid < DD) dsm[B3 + tid] = b3g[tid];
    if (tid >= DD && tid < 16) dsm[B3 + tid] = 0.f;

    // ---------------- x state init (fp32 master + tf32 copy) ----------------
    const int base = blockIdx.x * RPC;
    for (int idx = tid; idx < RPC * DD; idx += TPB) {
        int rr = idx >> 3, d = idx & 7;
        int grow = base + rr;
        float v = (grow < n) ? x0[grow * DD + d] : 0.f;
        dsm[OXF + rr * 8 + d] = v;
        dsm[OXT + rr * 12 + d] = tf32f(v);
    }
    __syncthreads();

    const int lane = tid & 31;
    const int warp = tid >> 5;
    const int g  = lane >> 2;     // 0..7
    const int t4 = lane & 3;      // 0..3
    const int wrow = warp * 32;   // this warp's first row (CTA-local)

    const int nsteps = nsp ? *nsp : 100;
    const float dt = 1.0f / (float)nsteps;

    float ldr00 = 0.f, ldr01 = 0.f, ldr10 = 0.f, ldr11 = 0.f;

    #pragma unroll 1
    for (int i = 0; i < nsteps; i++) {
        const float t = (float)i * dt;

        #pragma unroll 1
        for (int pass = 0; pass < 2; pass++) {
            // ---- layer 1: OH = tanh(x @ W1[:,0:8]^T + (b1 + t*W1[:,8])) ----
            {
                float c0[8][4], c1[8][4];
                #pragma unroll
                for (int nt = 0; nt < 8; nt++) {
                    const float2 bp = *(const float2*)&dsm[B1 + nt * 8 + 2 * t4];
                    const float2 wp = *(const float2*)&dsm[W1C8 + nt * 8 + 2 * t4];
                    const float v0 = fmaf(t, wp.x, bp.x);
                    const float v1 = fmaf(t, wp.y, bp.y);
                    c0[nt][0] = v0; c0[nt][1] = v1; c0[nt][2] = v0; c0[nt][3] = v1;
                    c1[nt][0] = v0; c1[nt][1] = v1; c1[nt][2] = v0; c1[nt][3] = v1;
                }
                unsigned aa[4], ab[4];
                LDA(aa, OXT, 12, wrow, 0)
                LDA(ab, OXT, 12, wrow + 16, 0)
                #pragma unroll
                for (int nt = 0; nt < 8; nt++) {
                    unsigned bb[2];
                    LDB(bb, PW1, 12, nt * 8, 0)
                    mma8(c0[nt], aa, bb);
                    mma8(c1[nt], ab, bb);
                }
                EPI_TANH(OH)
            }
            __syncwarp();

            // ---- layer 2: a2 = h1 @ W2^T + b2 ----
            {
                float c0[8][4], c1[8][4];
                BIAS_INIT(B2)
                GEMM64(OH, PW2F)
                if (pass == 0) {
                    EPI_TANH(OG)
                } else {
                    // fused: OG = w3s * (1 - tanh(a2)^2)   (ga2 for VJP)
                    #pragma unroll
                    for (int nt = 0; nt < 8; nt++) {
                        const int cc = nt * 8 + 2 * t4;
                        const float2 wz = *(const float2*)&dsm[W3S + cc];
                        GA2ST(wrow + g,      cc, c0[nt][0], c0[nt][1], wz)
                        GA2ST(wrow + 8 + g,  cc, c0[nt][2], c0[nt][3], wz)
                        GA2ST(wrow + 16 + g, cc, c1[nt][0], c1[nt][1], wz)
                        GA2ST(wrow + 24 + g, cc, c1[nt][2], c1[nt][3], wz)
                    }
                }
            }
            __syncwarp();

            // ---- layer 3 (pass 0 only): x += dt * (h2 @ W3^T + b3) ----
            if (pass == 0) {
                float d0[4], d1[4];
                {
                    const float2 bp = *(const float2*)&dsm[B3 + 2 * t4];
                    d0[0] = bp.x; d0[1] = bp.y; d0[2] = bp.x; d0[3] = bp.y;
                    d1[0] = bp.x; d1[1] = bp.y; d1[2] = bp.x; d1[3] = bp.y;
                }
                #pragma unroll 2
                for (int k0 = 0; k0 < 64; k0 += 8) {
                    unsigned aa[4], ab[4], bb[2];
                    LDA(aa, OG, 68, wrow, k0)
                    LDA(ab, OG, 68, wrow + 16, k0)
                    LDB(bb, PW3, 68, 0, k0)
                    mma8(d0, aa, bb);
                    mma8(d1, ab, bb);
                }
                // x update: rows (wrow+g, +8, +16, +24), cols {2t4, 2t4+1}
                #define XUPD(ROW, VA, VB) { \
                    float2 xv = *(float2*)&dsm[OXF + (ROW) * 8 + 2 * t4]; \
                    xv.x = fmaf(dt, VA, xv.x); \
                    xv.y = fmaf(dt, VB, xv.y); \
                    *(float2*)&dsm[OXF + (ROW) * 8 + 2 * t4] = xv; \
                    *(float2*)&dsm[OXT + (ROW) * 12 + 2 * t4] = \
                        make_float2(tf32f(xv.x), tf32f(xv.y)); }
                XUPD(wrow + g,      d0[0], d0[1])
                XUPD(wrow + 8 + g,  d0[2], d0[3])
                XUPD(wrow + 16 + g, d1[0], d1[1])
                XUPD(wrow + 24 + g, d1[2], d1[3])
                #undef XUPD
                __syncwarp();
            }
        }

        // ---- backward: gh1 = ga2 @ W2; fold tanh' and w1s into ld ----
        {
            float c0[8][4], c1[8][4];
            #pragma unroll
            for (int nt = 0; nt < 8; nt++)
                #pragma unroll
                for (int q = 0; q < 4; q++) { c0[nt][q] = 0.f; c1[nt][q] = 0.f; }
            GEMM64(OG, PW2B)

            float lp00 = 0.f, lp01 = 0.f, lp10 = 0.f, lp11 = 0.f;
            #pragma unroll
            for (int nt = 0; nt < 8; nt++) {
                const int cc = nt * 8 + 2 * t4;
                const float2 ws = *(const float2*)&dsm[W1S + cc];
                #define FOLD(ROW, VA, VB, LP) { \
                    const float2 hv = *(const float2*)&dsm[OH + (ROW) * 68 + cc]; \
                    float te = (VA) * ws.x; \
                    LP += te; LP = fmaf(-(te * hv.x), hv.x, LP); \
                    te = (VB) * ws.y; \
                    LP += te; LP = fmaf(-(te * hv.y), hv.y, LP); }
                FOLD(wrow + g,      c0[nt][0], c0[nt][1], lp00)
                FOLD(wrow + 8 + g,  c0[nt][2], c0[nt][3], lp01)
                FOLD(wrow + 16 + g, c1[nt][0], c1[nt][1], lp10)
                FOLD(wrow + 24 + g, c1[nt][2], c1[nt][3], lp11)
                #undef FOLD
            }
            // reduce over the 4 t4-lanes (lane bits 0..1)
            lp00 += __shfl_xor_sync(0xffffffffu, lp00, 1);
            lp00 += __shfl_xor_sync(0xffffffffu, lp00, 2);
            lp01 += __shfl_xor_sync(0xffffffffu, lp01, 1);
            lp01 += __shfl_xor_sync(0xffffffffu, lp01, 2);
            lp10 += __shfl_xor_sync(0xffffffffu, lp10, 1);
            lp10 += __shfl_xor_sync(0xffffffffu, lp10, 2);
            lp11 += __shfl_xor_sync(0xffffffffu, lp11, 1);
            lp11 += __shfl_xor_sync(0xffffffffu, lp11, 2);
            ldr00 = fmaf(dt, lp00, ldr00);
            ldr01 = fmaf(dt, lp01, ldr01);
            ldr10 = fmaf(dt, lp10, ldr10);
            ldr11 = fmaf(dt, lp11, ldr11);
        }
        __syncwarp();
    }

    // ---------------- output (t4==0 lanes own rows wrow+g+{0,8,16,24}) ----------------
    if (t4 == 0) {
        #define OUTROW(ROFF, LDV) { \
            const int lrow = wrow + (ROFF) + g; \
            const int grow = base + lrow; \
            if (grow < n) { \
                const float4 v0 = *(const float4*)&dsm[OXF + lrow * 8]; \
                const float4 v1 = *(const float4*)&dsm[OXF + lrow * 8 + 4]; \
                *(float4*)&out[grow * DD]     = v0; \
                *(float4*)&out[grow * DD + 4] = v1; \
                out[n * DD + grow] = (LDV); \
            } }
        OUTROW(0,  ldr00)
        OUTROW(8,  ldr01)
        OUTROW(16, ldr10)
        OUTROW(24, ldr11)
        #undef OUTROW
    }
}

extern "C" void kernel_launch(void* const* d_in, const int* in_sizes, int n_in,
                              void* d_out, int out_size) {
    const float* x0 = (const float*)d_in[0];
    const float* W1 = (const float*)d_in[1];
    const float* b1 = (const float*)d_in[2];
    const float* W2 = (const float*)d_in[3];
    const float* b2 = (const float*)d_in[4];
    const float* W3 = (const float*)d_in[5];
    const float* b3 = (const float*)d_in[6];
    const int* nsp = (n_in > 7) ? (const int*)d_in[7] : nullptr;

    cudaFuncSetAttribute(cnf_kernel,
                         cudaFuncAttributeMaxDynamicSharedMemorySize, SMEM_BYTES);

    int n = in_sizes[0] / DD;
    int blocks = (n + RPC - 1) / RPC;   // 147 for n=32768
    cnf_kernel<<<blocks, TPB, SMEM_BYTES>>>(x0, W1, b1, W2, b2, W3, b3, nsp,
                                            (float*)d_out, n);
}